// round 14
// baseline (speedup 1.0000x reference)
#include <cuda_runtime.h>
#include <cuda_fp16.h>
#include <stdint.h>

// ---------------------------------------------------------------------------
// Problem dims (fixed)
// ---------------------------------------------------------------------------
#define M_DIM 8192
#define N_DIM 4096
#define K_DIM 4224
#define KBYTES 2112   // K/2 packed bytes per row (one int32 per byte)
#define KBLKS  264    // K/16 scale blocks per row
#define TOTA (M_DIM * KBLKS)   // dequant work items for A
#define TOTB (N_DIM * KBLKS)   // for B

// GEMM tiling (legacy HMMA; tcgen05 unavailable at base sm_103 PTX target)
#define BM 128
#define BN 128
#define BK 64
#define NT 128                          // 4 warps: 2m x 2n, warp tile 64x64
#define KITERS 66                       // 4224 / 64 = 22 * 3
#define STAGES 3
#define AB (BM * BK * 2)                // 16384 bytes per A stage
#define BB (BN * BK * 2)                // 16384 bytes per B stage
#define STB (AB + BB)                   // 32768
#define SMEM_DYN (1024 + STAGES * STB + 64)  // tiles + mbarrier block

// ---------------------------------------------------------------------------
// Device scratch (allocation-free rule: __device__ globals), fp16 storage
// ---------------------------------------------------------------------------
__device__ __half g_A[(size_t)M_DIM * K_DIM];
__device__ __half g_B[(size_t)N_DIM * K_DIM];

// ---------------------------------------------------------------------------
// Dequant (A and B in one launch): packed fp4 * 2^(sf-127) -> fp16 row-major.
// Pure integer path: fp16 magnitude high-bytes via byte_perm LUT, sign merged
// by byte placement, exact mul.f16x2 by the power-of-two scale. Exact in fp16.
// ---------------------------------------------------------------------------
__global__ void dequant_kernel(const int* __restrict__ packedA,
                               const int* __restrict__ sfA,
                               const int* __restrict__ packedB,
                               const int* __restrict__ sfB) {
    int idx = blockIdx.x * blockDim.x + threadIdx.x;
    const int* packed;
    const int* sf;
    __half* out;
    if (idx < TOTA) {
        packed = packedA; sf = sfA; out = g_A;
    } else {
        idx -= TOTA;
        if (idx >= TOTB) return;
        packed = packedB; sf = sfB; out = g_B;
    }
    int r = idx / KBLKS;
    int b = idx - r * KBLKS;

    const int4* p = reinterpret_cast<const int4*>(packed + (size_t)r * KBYTES + b * 8);
    int4 p0 = p[0];
    int4 p1 = p[1];

    // fp16 scale = 2^(sf-127): exponent field = sf-112 (in [6,21])
    unsigned sbits = ((unsigned)(sf[(size_t)r * KBLKS + b] - 112)) << 10;
    unsigned scale2 = sbits | (sbits << 16);

    const unsigned LUTLO = 0x3E3C3800u;  // fp16 hi-bytes of {0,0.5,1,1.5}
    const unsigned LUTHI = 0x46444240u;  // fp16 hi-bytes of {2,3,4,6}

    int v[8] = {p0.x, p0.y, p0.z, p0.w, p1.x, p1.y, p1.z, p1.w};
    unsigned o[8];
#pragma unroll
    for (int i = 0; i < 8; i++) {
        unsigned vi = (unsigned)v[i];
        unsigned mags = __byte_perm(LUTLO, LUTHI, vi & 0x77u);
        unsigned ws = mags | ((vi & 8u) << 4) | ((vi & 0x80u) << 8);
        unsigned h = __byte_perm(ws, 0u, 0x1404u);
        unsigned rres;
        asm("mul.rn.f16x2 %0, %1, %2;" : "=r"(rres) : "r"(h), "r"(scale2));
        o[i] = rres;
    }
    uint4* dst = reinterpret_cast<uint4*>(out + (size_t)r * K_DIM + b * 16);
    dst[0] = make_uint4(o[0], o[1], o[2], o[3]);
    dst[1] = make_uint4(o[4], o[5], o[6], o[7]);
}

// ---------------------------------------------------------------------------
// Helpers
// ---------------------------------------------------------------------------
__device__ __forceinline__ uint32_t smem_u32(const void* p) {
    uint32_t a;
    asm("{ .reg .u64 t; cvta.to.shared.u64 t, %1; cvt.u32.u64 %0, t; }" : "=r"(a) : "l"(p));
    return a;
}

__device__ __forceinline__ void mbar_init(uint32_t a, uint32_t n) {
    asm volatile("mbarrier.init.shared.b64 [%0], %1;" :: "r"(a), "r"(n) : "memory");
}
__device__ __forceinline__ void mbar_arrive(uint32_t a) {
    asm volatile("mbarrier.arrive.shared.b64 _, [%0];" :: "r"(a) : "memory");
}
__device__ __forceinline__ void cp_arrive_noinc(uint32_t a) {
    asm volatile("cp.async.mbarrier.arrive.noinc.shared.b64 [%0];" :: "r"(a) : "memory");
}
__device__ __forceinline__ void mbar_wait(uint32_t a, uint32_t parity) {
    asm volatile(
        "{\n\t.reg .pred P;\n"
        "LW_%=:\n\t"
        "mbarrier.try_wait.parity.acquire.cta.shared::cta.b64 P, [%0], %1, 0x989680;\n\t"
        "@P bra LD_%=;\n\t"
        "bra LW_%=;\n"
        "LD_%=:\n\t}"
        :: "r"(a), "r"(parity) : "memory");
}

__device__ __forceinline__ void ldsm4(uint32_t* r, uint32_t addr) {
    asm volatile("ldmatrix.sync.aligned.m8n8.x4.shared.b16 {%0,%1,%2,%3}, [%4];"
                 : "=r"(r[0]), "=r"(r[1]), "=r"(r[2]), "=r"(r[3]) : "r"(addr));
}

__device__ __forceinline__ void mma16816(float* d, const uint32_t* a, const uint32_t* b) {
    asm volatile(
        "mma.sync.aligned.m16n8k16.row.col.f32.f16.f16.f32 "
        "{%0,%1,%2,%3}, {%4,%5,%6,%7}, {%8,%9}, {%0,%1,%2,%3};"
        : "+f"(d[0]), "+f"(d[1]), "+f"(d[2]), "+f"(d[3])
        : "r"(a[0]), "r"(a[1]), "r"(a[2]), "r"(a[3]), "r"(b[0]), "r"(b[1]));
}

// Swizzle: XOR bits[6:4] with bits[9:7] (128B rows, 16B granules)
__device__ __forceinline__ uint32_t swz(uint32_t off) {
    return off ^ ((off >> 3) & 0x70);
}

// Fill one (stage, kiter): A 128x64 fp16 (16KB) + B 128x64 fp16 (16KB), SW128.
// 128 threads x 16 cp.async(16B) each.
__device__ __forceinline__ void load_stage(uint32_t tiles, int stage, int kit,
                                           int m0, int n0, int tid) {
    uint32_t sbase = tiles + stage * STB;
    int k0 = kit * BK;
#pragma unroll
    for (int i = 0; i < 8; i++) {
        int c = tid + i * NT;             // 0..1023
        int row = c >> 3, seg = c & 7;
        const __half* src = g_A + (size_t)(m0 + row) * K_DIM + k0 + seg * 8;
        uint32_t dst = sbase + swz(row * 128 + seg * 16);
        asm volatile("cp.async.cg.shared.global [%0], [%1], 16;" :: "r"(dst), "l"(src));
    }
#pragma unroll
    for (int i = 0; i < 8; i++) {
        int c = tid + i * NT;
        int row = c >> 3, seg = c & 7;
        const __half* src = g_B + (size_t)(n0 + row) * K_DIM + k0 + seg * 8;
        uint32_t dst = sbase + AB + swz(row * 128 + seg * 16);
        asm volatile("cp.async.cg.shared.global [%0], [%1], 16;" :: "r"(dst), "l"(src));
    }
}

// ---------------------------------------------------------------------------
// fp16 GEMM via mma.sync: CTA 128x128, 4 warps (2m x 2n), warp tile 64x64,
// 3-stage mbarrier producer/consumer pipeline, 2 CTAs/SM. B fragments are
// double-buffered (fits the 256-reg cap; full double-buffer does not):
// per ks the order is B-LDSM(ks+1) -> MMA(ks) -> A-LDSM(ks+1), halving the
// exposed LDS chain at each ks boundary. Producer section hides under MMAs.
// ---------------------------------------------------------------------------
__global__ void __launch_bounds__(NT, 2)
gemm_kernel(const float* __restrict__ scale_p,
            const float* __restrict__ bias,
            float* __restrict__ out) {
    extern __shared__ char smem_raw[];
    uint32_t tiles = (smem_u32(smem_raw) + 1023) & ~1023u;
    uint32_t mbase = tiles + STAGES * STB;   // full[0..2], empty[0..2]
#define MBF(s) (mbase + (s) * 8)
#define MBE(s) (mbase + 24 + (s) * 8)

    int tid = threadIdx.x;
    int wid = tid >> 5;
    int lane = tid & 31;
    int m0 = blockIdx.y * BM;
    int n0 = blockIdx.x * BN;
    int wm = wid & 1;    // 2 m-slices of 64 rows
    int wn = wid >> 1;   // 2 n-slices of 64 cols

    // Precomputed swizzled fragment offsets (ks=0), relative to stage A/B base.
    // Per-ks address = base ^ (ks<<5): ks*32 hits bits[6:5] only; the lane
    // column bit is bit 4; swizzle mask occupies bits[6:4] -> pure XOR works.
    uint32_t arel[4], brel[4];
#pragma unroll
    for (int mf = 0; mf < 4; mf++) {
        int row = wm * 64 + mf * 16 + (lane & 15);
        uint32_t c = (lane >> 4) << 4;
        arel[mf] = row * 128 + (c ^ ((row & 7) << 4));
    }
#pragma unroll
    for (int np = 0; np < 4; np++) {
        int row = wn * 64 + np * 16 + (lane & 7) + ((lane >> 4) << 3);
        uint32_t c = ((lane >> 3) & 1) << 4;
        brel[np] = row * 128 + (c ^ ((row & 7) << 4));
    }

    float acc[4][8][4];
#pragma unroll
    for (int a = 0; a < 4; a++)
#pragma unroll
        for (int b = 0; b < 8; b++)
#pragma unroll
            for (int c = 0; c < 4; c++) acc[a][b][c] = 0.0f;

    // ---- mbarrier init ----
    if (tid == 0) {
#pragma unroll
        for (int s = 0; s < STAGES; s++) {
            mbar_init(MBF(s), NT);
            mbar_init(MBE(s), NT);
        }
    }
    __syncthreads();   // only hard barrier: after init
    // Pre-fire round-0 "empty" on all stages (flip #1 of each empty barrier)
#pragma unroll
    for (int s = 0; s < STAGES; s++) mbar_arrive(MBE(s));

    // Prologue: fill stages 0,1 (kit 0,1)
#pragma unroll
    for (int s = 0; s < 2; s++) {
        mbar_wait(MBE(s), 0);
        load_stage(tiles, s, s, m0, n0, tid);
        cp_arrive_noinc(MBF(s));
    }

    // Main loop: 22 macro-iters x 3 stages. Stage k consumed at iter 3m+k
    // (full parity m&1). Producer at iter it loads stage (it+2)%3 for round
    // r2=(it+2)/3, waiting empty parity r2&1: k=0 -> m&1, k=1,2 -> (m+1)&1.
    int ph = 0;
    for (int m = 0; m < KITERS / 3; m++) {
#pragma unroll
        for (int k = 0; k < 3; k++) {
            const int s = k;
            const int s2 = (k + 2) % 3;       // 2, 0, 1
            int it = 3 * m + k;
            int nit = it + 2;

            mbar_wait(MBF(s), ph);

            uint32_t abase = tiles + s * STB;
            uint32_t bbase = abase + AB;

            uint32_t afr[4][4];
            uint32_t bfr[2][8][2];

            // ks=0 frags (A single-buffered, B into buffer 0)
#pragma unroll
            for (int mf = 0; mf < 4; mf++)
                ldsm4(afr[mf], abase + arel[mf]);
#pragma unroll
            for (int np = 0; np < 4; np++) {
                uint32_t r[4];
                ldsm4(r, bbase + brel[np]);
                bfr[0][np * 2 + 0][0] = r[0]; bfr[0][np * 2 + 0][1] = r[1];
                bfr[0][np * 2 + 1][0] = r[2]; bfr[0][np * 2 + 1][1] = r[3];
            }

#pragma unroll
            for (int ks = 0; ks < 4; ks++) {
                int cur = ks & 1, nxt = cur ^ 1;
                uint32_t kxn = (uint32_t)((ks + 1) << 5);

                // Prefetch B(ks+1) before the MMA group (WAR-free: other buffer)
                if (ks < 3) {
#pragma unroll
                    for (int np = 0; np < 4; np++) {
                        uint32_t r[4];
                        ldsm4(r, bbase + (brel[np] ^ kxn));
                        bfr[nxt][np * 2 + 0][0] = r[0]; bfr[nxt][np * 2 + 0][1] = r[1];
                        bfr[nxt][np * 2 + 1][0] = r[2]; bfr[nxt][np * 2 + 1][1] = r[3];
                    }
                }

                // Producer section hidden under ks=0's in-flight MMAs
                if (ks == 1 && nit < KITERS) {
                    mbar_wait(MBE(s2), (k == 0) ? ph : (ph ^ 1));
                    load_stage(tiles, s2, nit, m0, n0, tid);
                    cp_arrive_noinc(MBF(s2));
                }

                if (ks == 3) mbar_arrive(MBE(s));  // all smem reads of s done

                // MMA group for ks
#pragma unroll
                for (int mf = 0; mf < 4; mf++)
#pragma unroll
                    for (int ng = 0; ng < 8; ng++)
                        mma16816(acc[mf][ng], afr[mf], bfr[cur][ng]);

                // Reload A for ks+1 (after MMAs that consumed afr)
                if (ks < 3) {
#pragma unroll
                    for (int mf = 0; mf < 4; mf++)
                        ldsm4(afr[mf], abase + (arel[mf] ^ kxn));
                }
            }
        }
        ph ^= 1;
    }

    // Epilogue: scale * acc + bias, f32 out (row-major [M, N])
    float sc = __ldg(scale_p);
#pragma unroll
    for (int mf = 0; mf < 4; mf++) {
#pragma unroll
        for (int ng = 0; ng < 8; ng++) {
            int m = m0 + wm * 64 + mf * 16 + (lane >> 2);
            int n = n0 + wn * 64 + ng * 8 + (lane & 3) * 2;
            float2 bb = *reinterpret_cast<const float2*>(bias + n);
            float2 v;
            v.x = acc[mf][ng][0] * sc + bb.x;
            v.y = acc[mf][ng][1] * sc + bb.y;
            *reinterpret_cast<float2*>(out + (size_t)m * N_DIM + n) = v;
            v.x = acc[mf][ng][2] * sc + bb.x;
            v.y = acc[mf][ng][3] * sc + bb.y;
            *reinterpret_cast<float2*>(out + (size_t)(m + 8) * N_DIM + n) = v;
        }
    }
#undef MBF
#undef MBE
}

// ---------------------------------------------------------------------------
// Launch
// ---------------------------------------------------------------------------
extern "C" void kernel_launch(void* const* d_in, const int* in_sizes, int n_in,
                              void* d_out, int out_size) {
    const int*   A_packed = (const int*)d_in[0];
    const int*   SFA      = (const int*)d_in[1];
    const float* scale    = (const float*)d_in[2];
    const int*   B_packed = (const int*)d_in[3];
    const int*   SFB      = (const int*)d_in[4];
    const float* bias     = (const float*)d_in[5];
    float*       out      = (float*)d_out;

    int tot = TOTA + TOTB;
    dequant_kernel<<<(tot + 255) / 256, 256>>>(A_packed, SFA, B_packed, SFB);

    static int configured = 0;
    if (!configured) {
        cudaFuncSetAttribute(gemm_kernel, cudaFuncAttributeMaxDynamicSharedMemorySize, SMEM_DYN);
        configured = 1;
    }
    dim3 grid(N_DIM / BN, M_DIM / BM);  // (32, 64)
    gemm_kernel<<<grid, NT, SMEM_DYN>>>(scale, bias, out);
}

// round 15
// speedup vs baseline: 1.0224x; 1.0224x over previous
#include <cuda_runtime.h>
#include <cuda_fp16.h>
#include <stdint.h>

// ---------------------------------------------------------------------------
// Problem dims (fixed)
// ---------------------------------------------------------------------------
#define M_DIM 8192
#define N_DIM 4096
#define K_DIM 4224
#define KBYTES 2112   // K/2 packed bytes per row (one int32 per byte)
#define KBLKS  264    // K/16 scale blocks per row
#define TOTA (M_DIM * KBLKS)   // dequant work items for A
#define TOTB (N_DIM * KBLKS)   // for B

// GEMM tiling (legacy HMMA; tcgen05 unavailable at base sm_103 PTX target)
#define BM 128
#define BN 128
#define BK 64
#define NT 128                          // 4 warps: 2m x 2n, warp tile 64x64
#define KITERS 66                       // 4224 / 64 = 22 * 3
#define STAGES 3
#define AB (BM * BK * 2)                // 16384 bytes per A stage
#define BB (BN * BK * 2)                // 16384 bytes per B stage
#define STB (AB + BB)                   // 32768
#define SMEM_DYN (1024 + STAGES * STB + 64)  // tiles + mbarrier block

// ---------------------------------------------------------------------------
// Device scratch (allocation-free rule: __device__ globals), fp16 storage
// ---------------------------------------------------------------------------
__device__ __half g_A[(size_t)M_DIM * K_DIM];
__device__ __half g_B[(size_t)N_DIM * K_DIM];

// ---------------------------------------------------------------------------
// Dequant (A and B in one launch): packed fp4 * 2^(sf-127) -> fp16 row-major.
// Pure integer path: fp16 magnitude high-bytes via byte_perm LUT, sign merged
// by byte placement, exact mul.f16x2 by the power-of-two scale. Exact in fp16.
// ---------------------------------------------------------------------------
__global__ void dequant_kernel(const int* __restrict__ packedA,
                               const int* __restrict__ sfA,
                               const int* __restrict__ packedB,
                               const int* __restrict__ sfB) {
    int idx = blockIdx.x * blockDim.x + threadIdx.x;
    const int* packed;
    const int* sf;
    __half* out;
    if (idx < TOTA) {
        packed = packedA; sf = sfA; out = g_A;
    } else {
        idx -= TOTA;
        if (idx >= TOTB) return;
        packed = packedB; sf = sfB; out = g_B;
    }
    int r = idx / KBLKS;
    int b = idx - r * KBLKS;

    const int4* p = reinterpret_cast<const int4*>(packed + (size_t)r * KBYTES + b * 8);
    int4 p0 = p[0];
    int4 p1 = p[1];

    // fp16 scale = 2^(sf-127): exponent field = sf-112 (in [6,21])
    unsigned sbits = ((unsigned)(sf[(size_t)r * KBLKS + b] - 112)) << 10;
    unsigned scale2 = sbits | (sbits << 16);

    const unsigned LUTLO = 0x3E3C3800u;  // fp16 hi-bytes of {0,0.5,1,1.5}
    const unsigned LUTHI = 0x46444240u;  // fp16 hi-bytes of {2,3,4,6}

    int v[8] = {p0.x, p0.y, p0.z, p0.w, p1.x, p1.y, p1.z, p1.w};
    unsigned o[8];
#pragma unroll
    for (int i = 0; i < 8; i++) {
        unsigned vi = (unsigned)v[i];
        unsigned mags = __byte_perm(LUTLO, LUTHI, vi & 0x77u);
        unsigned ws = mags | ((vi & 8u) << 4) | ((vi & 0x80u) << 8);
        unsigned h = __byte_perm(ws, 0u, 0x1404u);
        unsigned rres;
        asm("mul.rn.f16x2 %0, %1, %2;" : "=r"(rres) : "r"(h), "r"(scale2));
        o[i] = rres;
    }
    uint4* dst = reinterpret_cast<uint4*>(out + (size_t)r * K_DIM + b * 16);
    dst[0] = make_uint4(o[0], o[1], o[2], o[3]);
    dst[1] = make_uint4(o[4], o[5], o[6], o[7]);
}

// ---------------------------------------------------------------------------
// Helpers
// ---------------------------------------------------------------------------
__device__ __forceinline__ uint32_t smem_u32(const void* p) {
    uint32_t a;
    asm("{ .reg .u64 t; cvta.to.shared.u64 t, %1; cvt.u32.u64 %0, t; }" : "=r"(a) : "l"(p));
    return a;
}

__device__ __forceinline__ void mbar_init(uint32_t a, uint32_t n) {
    asm volatile("mbarrier.init.shared.b64 [%0], %1;" :: "r"(a), "r"(n) : "memory");
}
__device__ __forceinline__ void mbar_arrive(uint32_t a) {
    asm volatile("mbarrier.arrive.shared.b64 _, [%0];" :: "r"(a) : "memory");
}
__device__ __forceinline__ void cp_arrive_noinc(uint32_t a) {
    asm volatile("cp.async.mbarrier.arrive.noinc.shared.b64 [%0];" :: "r"(a) : "memory");
}
__device__ __forceinline__ void mbar_wait(uint32_t a, uint32_t parity) {
    asm volatile(
        "{\n\t.reg .pred P;\n"
        "LW_%=:\n\t"
        "mbarrier.try_wait.parity.acquire.cta.shared::cta.b64 P, [%0], %1, 0x989680;\n\t"
        "@P bra LD_%=;\n\t"
        "bra LW_%=;\n"
        "LD_%=:\n\t}"
        :: "r"(a), "r"(parity) : "memory");
}

__device__ __forceinline__ void ldsm4(uint32_t* r, uint32_t addr) {
    asm volatile("ldmatrix.sync.aligned.m8n8.x4.shared.b16 {%0,%1,%2,%3}, [%4];"
                 : "=r"(r[0]), "=r"(r[1]), "=r"(r[2]), "=r"(r[3]) : "r"(addr));
}

__device__ __forceinline__ void mma16816(float* d, const uint32_t* a, const uint32_t* b) {
    asm volatile(
        "mma.sync.aligned.m16n8k16.row.col.f32.f16.f16.f32 "
        "{%0,%1,%2,%3}, {%4,%5,%6,%7}, {%8,%9}, {%0,%1,%2,%3};"
        : "+f"(d[0]), "+f"(d[1]), "+f"(d[2]), "+f"(d[3])
        : "r"(a[0]), "r"(a[1]), "r"(a[2]), "r"(a[3]), "r"(b[0]), "r"(b[1]));
}

// Swizzle: XOR bits[6:4] with bits[9:7] (128B rows, 16B granules)
__device__ __forceinline__ uint32_t swz(uint32_t off) {
    return off ^ ((off >> 3) & 0x70);
}

// Fill one (stage, kiter): A 128x64 fp16 (16KB) + B 128x64 fp16 (16KB), SW128.
// 128 threads x 16 cp.async(16B) each.
__device__ __forceinline__ void load_stage(uint32_t tiles, int stage, int kit,
                                           int m0, int n0, int tid) {
    uint32_t sbase = tiles + stage * STB;
    int k0 = kit * BK;
#pragma unroll
    for (int i = 0; i < 8; i++) {
        int c = tid + i * NT;             // 0..1023
        int row = c >> 3, seg = c & 7;
        const __half* src = g_A + (size_t)(m0 + row) * K_DIM + k0 + seg * 8;
        uint32_t dst = sbase + swz(row * 128 + seg * 16);
        asm volatile("cp.async.cg.shared.global [%0], [%1], 16;" :: "r"(dst), "l"(src));
    }
#pragma unroll
    for (int i = 0; i < 8; i++) {
        int c = tid + i * NT;
        int row = c >> 3, seg = c & 7;
        const __half* src = g_B + (size_t)(n0 + row) * K_DIM + k0 + seg * 8;
        uint32_t dst = sbase + AB + swz(row * 128 + seg * 16);
        asm volatile("cp.async.cg.shared.global [%0], [%1], 16;" :: "r"(dst), "l"(src));
    }
}

// ---------------------------------------------------------------------------
// fp16 GEMM via mma.sync: CTA 128x128, 4 warps (2m x 2n), warp tile 64x64,
// 3-stage mbarrier producer/consumer pipeline, 2 CTAs/SM (R13 structure).
// New: the consumer full-wait is software-pipelined across iterations — the
// wait for stage s_next is issued mid-body (after the ks=1 MMA group) of the
// previous iteration, so its ~90-cyc fast path and any residual cp.async
// latency hide under MMAs instead of heading the next iteration.
// ---------------------------------------------------------------------------
__global__ void __launch_bounds__(NT, 2)
gemm_kernel(const float* __restrict__ scale_p,
            const float* __restrict__ bias,
            float* __restrict__ out) {
    extern __shared__ char smem_raw[];
    uint32_t tiles = (smem_u32(smem_raw) + 1023) & ~1023u;
    uint32_t mbase = tiles + STAGES * STB;   // full[0..2], empty[0..2]
#define MBF(s) (mbase + (s) * 8)
#define MBE(s) (mbase + 24 + (s) * 8)

    int tid = threadIdx.x;
    int wid = tid >> 5;
    int lane = tid & 31;
    int m0 = blockIdx.y * BM;
    int n0 = blockIdx.x * BN;
    int wm = wid & 1;    // 2 m-slices of 64 rows
    int wn = wid >> 1;   // 2 n-slices of 64 cols

    // Precomputed swizzled fragment offsets (ks=0), relative to stage A/B base.
    // Per-ks address = base ^ (ks<<5): ks*32 hits bits[6:5] only; the lane
    // column bit is bit 4; swizzle mask occupies bits[6:4] -> pure XOR works.
    uint32_t arel[4], brel[4];
#pragma unroll
    for (int mf = 0; mf < 4; mf++) {
        int row = wm * 64 + mf * 16 + (lane & 15);
        uint32_t c = (lane >> 4) << 4;
        arel[mf] = row * 128 + (c ^ ((row & 7) << 4));
    }
#pragma unroll
    for (int np = 0; np < 4; np++) {
        int row = wn * 64 + np * 16 + (lane & 7) + ((lane >> 4) << 3);
        uint32_t c = ((lane >> 3) & 1) << 4;
        brel[np] = row * 128 + (c ^ ((row & 7) << 4));
    }

    float acc[4][8][4];
#pragma unroll
    for (int a = 0; a < 4; a++)
#pragma unroll
        for (int b = 0; b < 8; b++)
#pragma unroll
            for (int c = 0; c < 4; c++) acc[a][b][c] = 0.0f;

    // ---- mbarrier init ----
    if (tid == 0) {
#pragma unroll
        for (int s = 0; s < STAGES; s++) {
            mbar_init(MBF(s), NT);
            mbar_init(MBE(s), NT);
        }
    }
    __syncthreads();   // only hard barrier: after init
    // Pre-fire round-0 "empty" on all stages (flip #1 of each empty barrier)
#pragma unroll
    for (int s = 0; s < STAGES; s++) mbar_arrive(MBE(s));

    // Prologue: fill stages 0,1 (kit 0,1)
#pragma unroll
    for (int s = 0; s < 2; s++) {
        mbar_wait(MBE(s), 0);
        load_stage(tiles, s, s, m0, n0, tid);
        cp_arrive_noinc(MBF(s));
    }

    // Peeled consumer wait for the first iteration's stage.
    mbar_wait(MBF(0), 0);

    // Main loop: 22 macro-iters x 3 stages. Stage k consumed at iter 3m+k
    // (full parity m&1). Producer at iter it loads stage (it+2)%3 for round
    // r2=(it+2)/3, waiting empty parity r2&1: k=0 -> m&1, k=1,2 -> (m+1)&1.
    // Consumer full-wait for stage (k+1)%3 is hoisted into this body.
    int ph = 0;
    for (int m = 0; m < KITERS / 3; m++) {
#pragma unroll
        for (int k = 0; k < 3; k++) {
            const int s = k;
            const int s2 = (k + 2) % 3;       // producer target: 2, 0, 1
            const int snx = (k + 1) % 3;      // next consumer stage
            int it = 3 * m + k;
            int nit = it + 2;

            uint32_t abase = tiles + s * STB;
            uint32_t bbase = abase + AB;

            // ---- ks = 0: load frags + MMA (stage s already full-waited) ----
            uint32_t afr[4][4];
            uint32_t bfr[8][2];
#pragma unroll
            for (int mf = 0; mf < 4; mf++)
                ldsm4(afr[mf], abase + arel[mf]);
#pragma unroll
            for (int np = 0; np < 4; np++) {
                uint32_t r[4];
                ldsm4(r, bbase + brel[np]);
                bfr[np * 2 + 0][0] = r[0]; bfr[np * 2 + 0][1] = r[1];
                bfr[np * 2 + 1][0] = r[2]; bfr[np * 2 + 1][1] = r[3];
            }
#pragma unroll
            for (int mf = 0; mf < 4; mf++)
#pragma unroll
                for (int ng = 0; ng < 8; ng++)
                    mma16816(acc[mf][ng], afr[mf], bfr[ng]);

            // ---- producer section, hidden under in-flight MMAs ----
            if (nit < KITERS) {
                mbar_wait(MBE(s2), (k == 0) ? ph : (ph ^ 1));
                load_stage(tiles, s2, nit, m0, n0, tid);
                cp_arrive_noinc(MBF(s2));
            }

            // ---- ks = 1..3 ----
#pragma unroll
            for (int ks = 1; ks < 4; ks++) {
                uint32_t kx = (uint32_t)(ks << 5);
#pragma unroll
                for (int mf = 0; mf < 4; mf++)
                    ldsm4(afr[mf], abase + (arel[mf] ^ kx));
#pragma unroll
                for (int np = 0; np < 4; np++) {
                    uint32_t r[4];
                    ldsm4(r, bbase + (brel[np] ^ kx));
                    bfr[np * 2 + 0][0] = r[0]; bfr[np * 2 + 0][1] = r[1];
                    bfr[np * 2 + 1][0] = r[2]; bfr[np * 2 + 1][1] = r[3];
                }
                if (ks == 3) mbar_arrive(MBE(s));  // all smem reads of s done
#pragma unroll
                for (int mf = 0; mf < 4; mf++)
#pragma unroll
                    for (int ng = 0; ng < 8; ng++)
                        mma16816(acc[mf][ng], afr[mf], bfr[ng]);

                // Hoisted consumer wait for the NEXT iteration's stage:
                // overlaps its ~90-cyc fast path (or residual data latency)
                // with the remaining ks=2,3 MMA groups.
                if (ks == 1 && it + 1 < KITERS) {
                    mbar_wait(MBF(snx), (k == 2) ? (ph ^ 1) : ph);
                }
            }
        }
        ph ^= 1;
    }

    // Epilogue: scale * acc + bias, f32 out (row-major [M, N])
    float sc = __ldg(scale_p);
#pragma unroll
    for (int mf = 0; mf < 4; mf++) {
#pragma unroll
        for (int ng = 0; ng < 8; ng++) {
            int m = m0 + wm * 64 + mf * 16 + (lane >> 2);
            int n = n0 + wn * 64 + ng * 8 + (lane & 3) * 2;
            float2 bb = *reinterpret_cast<const float2*>(bias + n);
            float2 v;
            v.x = acc[mf][ng][0] * sc + bb.x;
            v.y = acc[mf][ng][1] * sc + bb.y;
            *reinterpret_cast<float2*>(out + (size_t)m * N_DIM + n) = v;
            v.x = acc[mf][ng][2] * sc + bb.x;
            v.y = acc[mf][ng][3] * sc + bb.y;
            *reinterpret_cast<float2*>(out + (size_t)(m + 8) * N_DIM + n) = v;
        }
    }
#undef MBF
#undef MBE
}

// ---------------------------------------------------------------------------
// Launch
// ---------------------------------------------------------------------------
extern "C" void kernel_launch(void* const* d_in, const int* in_sizes, int n_in,
                              void* d_out, int out_size) {
    const int*   A_packed = (const int*)d_in[0];
    const int*   SFA      = (const int*)d_in[1];
    const float* scale    = (const float*)d_in[2];
    const int*   B_packed = (const int*)d_in[3];
    const int*   SFB      = (const int*)d_in[4];
    const float* bias     = (const float*)d_in[5];
    float*       out      = (float*)d_out;

    int tot = TOTA + TOTB;
    dequant_kernel<<<(tot + 255) / 256, 256>>>(A_packed, SFA, B_packed, SFB);

    static int configured = 0;
    if (!configured) {
        cudaFuncSetAttribute(gemm_kernel, cudaFuncAttributeMaxDynamicSharedMemorySize, SMEM_DYN);
        configured = 1;
    }
    dim3 grid(N_DIM / BN, M_DIM / BM);  // (32, 64)
    gemm_kernel<<<grid, NT, SMEM_DYN>>>(scale, bias, out);
}

// round 16
// speedup vs baseline: 1.0567x; 1.0335x over previous
#include <cuda_runtime.h>
#include <cuda_fp16.h>
#include <stdint.h>

// ---------------------------------------------------------------------------
// Problem dims (fixed)
// ---------------------------------------------------------------------------
#define M_DIM 8192
#define N_DIM 4096
#define K_DIM 4224
#define KBYTES 2112   // K/2 packed bytes per row (one int32 per byte)
#define KBLKS  264    // K/16 scale blocks per row
#define TOTA (M_DIM * KBLKS)   // dequant work items for A
#define TOTB (N_DIM * KBLKS)   // for B

// GEMM tiling (legacy HMMA; tcgen05 unavailable at base sm_103 PTX target)
#define BM 128
#define BN 128
#define BK 64
#define NT 128                          // 4 warps: 2m x 2n, warp tile 64x64
#define KITERS 66                       // 4224 / 64 = 22 * 3
#define STAGES 3
#define AB (BM * BK * 2)                // 16384 bytes per A stage
#define BB (BN * BK * 2)                // 16384 bytes per B stage
#define STB (AB + BB)                   // 32768
#define SMEM_DYN (1024 + STAGES * STB + 64)  // tiles + mbarrier block

// ---------------------------------------------------------------------------
// Device scratch (allocation-free rule: __device__ globals), fp16 storage
// ---------------------------------------------------------------------------
__device__ __half g_A[(size_t)M_DIM * K_DIM];
__device__ __half g_B[(size_t)N_DIM * K_DIM];

// ---------------------------------------------------------------------------
// Dequant (A and B in one launch): packed fp4 * 2^(sf-127) -> fp16 row-major.
// Pure integer path: fp16 magnitude high-bytes via byte_perm LUT, sign merged
// by byte placement, exact mul.f16x2 by the power-of-two scale. Exact in fp16.
// ---------------------------------------------------------------------------
__global__ void dequant_kernel(const int* __restrict__ packedA,
                               const int* __restrict__ sfA,
                               const int* __restrict__ packedB,
                               const int* __restrict__ sfB) {
    int idx = blockIdx.x * blockDim.x + threadIdx.x;
    const int* packed;
    const int* sf;
    __half* out;
    if (idx < TOTA) {
        packed = packedA; sf = sfA; out = g_A;
    } else {
        idx -= TOTA;
        if (idx >= TOTB) return;
        packed = packedB; sf = sfB; out = g_B;
    }
    int r = idx / KBLKS;
    int b = idx - r * KBLKS;

    const int4* p = reinterpret_cast<const int4*>(packed + (size_t)r * KBYTES + b * 8);
    int4 p0 = p[0];
    int4 p1 = p[1];

    // fp16 scale = 2^(sf-127): exponent field = sf-112 (in [6,21])
    unsigned sbits = ((unsigned)(sf[(size_t)r * KBLKS + b] - 112)) << 10;
    unsigned scale2 = sbits | (sbits << 16);

    const unsigned LUTLO = 0x3E3C3800u;  // fp16 hi-bytes of {0,0.5,1,1.5}
    const unsigned LUTHI = 0x46444240u;  // fp16 hi-bytes of {2,3,4,6}

    int v[8] = {p0.x, p0.y, p0.z, p0.w, p1.x, p1.y, p1.z, p1.w};
    unsigned o[8];
#pragma unroll
    for (int i = 0; i < 8; i++) {
        unsigned vi = (unsigned)v[i];
        unsigned mags = __byte_perm(LUTLO, LUTHI, vi & 0x77u);
        unsigned ws = mags | ((vi & 8u) << 4) | ((vi & 0x80u) << 8);
        unsigned h = __byte_perm(ws, 0u, 0x1404u);
        unsigned rres;
        asm("mul.rn.f16x2 %0, %1, %2;" : "=r"(rres) : "r"(h), "r"(scale2));
        o[i] = rres;
    }
    uint4* dst = reinterpret_cast<uint4*>(out + (size_t)r * K_DIM + b * 16);
    dst[0] = make_uint4(o[0], o[1], o[2], o[3]);
    dst[1] = make_uint4(o[4], o[5], o[6], o[7]);
}

// ---------------------------------------------------------------------------
// Helpers
// ---------------------------------------------------------------------------
__device__ __forceinline__ uint32_t smem_u32(const void* p) {
    uint32_t a;
    asm("{ .reg .u64 t; cvta.to.shared.u64 t, %1; cvt.u32.u64 %0, t; }" : "=r"(a) : "l"(p));
    return a;
}

__device__ __forceinline__ void mbar_init(uint32_t a, uint32_t n) {
    asm volatile("mbarrier.init.shared.b64 [%0], %1;" :: "r"(a), "r"(n) : "memory");
}
__device__ __forceinline__ void mbar_arrive(uint32_t a) {
    asm volatile("mbarrier.arrive.shared.b64 _, [%0];" :: "r"(a) : "memory");
}
__device__ __forceinline__ void cp_arrive_noinc(uint32_t a) {
    asm volatile("cp.async.mbarrier.arrive.noinc.shared.b64 [%0];" :: "r"(a) : "memory");
}
__device__ __forceinline__ void mbar_wait(uint32_t a, uint32_t parity) {
    asm volatile(
        "{\n\t.reg .pred P;\n"
        "LW_%=:\n\t"
        "mbarrier.try_wait.parity.acquire.cta.shared::cta.b64 P, [%0], %1, 0x989680;\n\t"
        "@P bra LD_%=;\n\t"
        "bra LW_%=;\n"
        "LD_%=:\n\t}"
        :: "r"(a), "r"(parity) : "memory");
}

__device__ __forceinline__ void ldsm4(uint32_t* r, uint32_t addr) {
    asm volatile("ldmatrix.sync.aligned.m8n8.x4.shared.b16 {%0,%1,%2,%3}, [%4];"
                 : "=r"(r[0]), "=r"(r[1]), "=r"(r[2]), "=r"(r[3]) : "r"(addr));
}

__device__ __forceinline__ void mma16816(float* d, const uint32_t* a, const uint32_t* b) {
    asm volatile(
        "mma.sync.aligned.m16n8k16.row.col.f32.f16.f16.f32 "
        "{%0,%1,%2,%3}, {%4,%5,%6,%7}, {%8,%9}, {%0,%1,%2,%3};"
        : "+f"(d[0]), "+f"(d[1]), "+f"(d[2]), "+f"(d[3])
        : "r"(a[0]), "r"(a[1]), "r"(a[2]), "r"(a[3]), "r"(b[0]), "r"(b[1]));
}

// Swizzle: XOR bits[6:4] with bits[9:7] (128B rows, 16B granules)
__device__ __forceinline__ uint32_t swz(uint32_t off) {
    return off ^ ((off >> 3) & 0x70);
}

// Fill HALF a stage: A tile 128x64 fp16 (16KB) or B tile (16KB), SW128.
// 128 threads x 8 cp.async(16B) each per half. Splitting the issue burst
// across two MMA groups spreads warp issue-slot and LSU pressure.
__device__ __forceinline__ void load_stage_a(uint32_t tiles, int stage, int kit,
                                             int m0, int tid) {
    uint32_t sbase = tiles + stage * STB;
    int k0 = kit * BK;
#pragma unroll
    for (int i = 0; i < 8; i++) {
        int c = tid + i * NT;             // 0..1023
        int row = c >> 3, seg = c & 7;
        const __half* src = g_A + (size_t)(m0 + row) * K_DIM + k0 + seg * 8;
        uint32_t dst = sbase + swz(row * 128 + seg * 16);
        asm volatile("cp.async.cg.shared.global [%0], [%1], 16;" :: "r"(dst), "l"(src));
    }
}
__device__ __forceinline__ void load_stage_b(uint32_t tiles, int stage, int kit,
                                             int n0, int tid) {
    uint32_t sbase = tiles + stage * STB;
    int k0 = kit * BK;
#pragma unroll
    for (int i = 0; i < 8; i++) {
        int c = tid + i * NT;
        int row = c >> 3, seg = c & 7;
        const __half* src = g_B + (size_t)(n0 + row) * K_DIM + k0 + seg * 8;
        uint32_t dst = sbase + AB + swz(row * 128 + seg * 16);
        asm volatile("cp.async.cg.shared.global [%0], [%1], 16;" :: "r"(dst), "l"(src));
    }
}

// ---------------------------------------------------------------------------
// fp16 GEMM via mma.sync: CTA 128x128, 4 warps (2m x 2n), warp tile 64x64,
// 3-stage mbarrier producer/consumer pipeline, 2 CTAs/SM (R13 structure).
// Producer section is split in two: A-tile cp.asyncs after the ks=0 MMA
// group, B-tile cp.asyncs + cp-arrive after the ks=1 group, spreading the
// 16-deep cp.async issue burst across two MMA groups.
// ---------------------------------------------------------------------------
__global__ void __launch_bounds__(NT, 2)
gemm_kernel(const float* __restrict__ scale_p,
            const float* __restrict__ bias,
            float* __restrict__ out) {
    extern __shared__ char smem_raw[];
    uint32_t tiles = (smem_u32(smem_raw) + 1023) & ~1023u;
    uint32_t mbase = tiles + STAGES * STB;   // full[0..2], empty[0..2]
#define MBF(s) (mbase + (s) * 8)
#define MBE(s) (mbase + 24 + (s) * 8)

    int tid = threadIdx.x;
    int wid = tid >> 5;
    int lane = tid & 31;
    int m0 = blockIdx.y * BM;
    int n0 = blockIdx.x * BN;
    int wm = wid & 1;    // 2 m-slices of 64 rows
    int wn = wid >> 1;   // 2 n-slices of 64 cols

    // Precomputed swizzled fragment offsets (ks=0), relative to stage A/B base.
    // Per-ks address = base ^ (ks<<5): ks*32 hits bits[6:5] only; the lane
    // column bit is bit 4; swizzle mask occupies bits[6:4] -> pure XOR works.
    uint32_t arel[4], brel[4];
#pragma unroll
    for (int mf = 0; mf < 4; mf++) {
        int row = wm * 64 + mf * 16 + (lane & 15);
        uint32_t c = (lane >> 4) << 4;
        arel[mf] = row * 128 + (c ^ ((row & 7) << 4));
    }
#pragma unroll
    for (int np = 0; np < 4; np++) {
        int row = wn * 64 + np * 16 + (lane & 7) + ((lane >> 4) << 3);
        uint32_t c = ((lane >> 3) & 1) << 4;
        brel[np] = row * 128 + (c ^ ((row & 7) << 4));
    }

    float acc[4][8][4];
#pragma unroll
    for (int a = 0; a < 4; a++)
#pragma unroll
        for (int b = 0; b < 8; b++)
#pragma unroll
            for (int c = 0; c < 4; c++) acc[a][b][c] = 0.0f;

    // ---- mbarrier init ----
    if (tid == 0) {
#pragma unroll
        for (int s = 0; s < STAGES; s++) {
            mbar_init(MBF(s), NT);
            mbar_init(MBE(s), NT);
        }
    }
    __syncthreads();   // only hard barrier: after init
    // Pre-fire round-0 "empty" on all stages (flip #1 of each empty barrier)
#pragma unroll
    for (int s = 0; s < STAGES; s++) mbar_arrive(MBE(s));

    // Prologue: fill stages 0,1 (kit 0,1)
#pragma unroll
    for (int s = 0; s < 2; s++) {
        mbar_wait(MBE(s), 0);
        load_stage_a(tiles, s, s, m0, tid);
        load_stage_b(tiles, s, s, n0, tid);
        cp_arrive_noinc(MBF(s));
    }

    // Main loop: 22 macro-iters x 3 stages. Stage k consumed at iter 3m+k
    // (full parity m&1). Producer at iter it loads stage (it+2)%3 for round
    // r2=(it+2)/3, waiting empty parity r2&1: k=0 -> m&1, k=1,2 -> (m+1)&1.
    int ph = 0;
    for (int m = 0; m < KITERS / 3; m++) {
#pragma unroll
        for (int k = 0; k < 3; k++) {
            const int s = k;
            const int s2 = (k + 2) % 3;       // 2, 0, 1
            int it = 3 * m + k;
            int nit = it + 2;

            mbar_wait(MBF(s), ph);

            uint32_t abase = tiles + s * STB;
            uint32_t bbase = abase + AB;

            // ---- ks = 0: load frags + MMA (gets tensor pipe busy ASAP) ----
            uint32_t afr[4][4];
            uint32_t bfr[8][2];
#pragma unroll
            for (int mf = 0; mf < 4; mf++)
                ldsm4(afr[mf], abase + arel[mf]);
#pragma unroll
            for (int np = 0; np < 4; np++) {
                uint32_t r[4];
                ldsm4(r, bbase + brel[np]);
                bfr[np * 2 + 0][0] = r[0]; bfr[np * 2 + 0][1] = r[1];
                bfr[np * 2 + 1][0] = r[2]; bfr[np * 2 + 1][1] = r[3];
            }
#pragma unroll
            for (int mf = 0; mf < 4; mf++)
#pragma unroll
                for (int ng = 0; ng < 8; ng++)
                    mma16816(acc[mf][ng], afr[mf], bfr[ng]);

            // ---- producer half 1 (A tile), hidden under in-flight MMAs ----
            if (nit < KITERS) {
                mbar_wait(MBE(s2), (k == 0) ? ph : (ph ^ 1));
                load_stage_a(tiles, s2, nit, m0, tid);
            }

            // ---- ks = 1..3 ----
#pragma unroll
            for (int ks = 1; ks < 4; ks++) {
                uint32_t kx = (uint32_t)(ks << 5);
#pragma unroll
                for (int mf = 0; mf < 4; mf++)
                    ldsm4(afr[mf], abase + (arel[mf] ^ kx));
#pragma unroll
                for (int np = 0; np < 4; np++) {
                    uint32_t r[4];
                    ldsm4(r, bbase + (brel[np] ^ kx));
                    bfr[np * 2 + 0][0] = r[0]; bfr[np * 2 + 0][1] = r[1];
                    bfr[np * 2 + 1][0] = r[2]; bfr[np * 2 + 1][1] = r[3];
                }
                if (ks == 3) mbar_arrive(MBE(s));  // all smem reads of s done
#pragma unroll
                for (int mf = 0; mf < 4; mf++)
#pragma unroll
                    for (int ng = 0; ng < 8; ng++)
                        mma16816(acc[mf][ng], afr[mf], bfr[ng]);

                // ---- producer half 2 (B tile + arrive) after ks=1 MMAs ----
                if (ks == 1 && nit < KITERS) {
                    load_stage_b(tiles, s2, nit, n0, tid);
                    cp_arrive_noinc(MBF(s2));
                }
            }
        }
        ph ^= 1;
    }

    // Epilogue: scale * acc + bias, f32 out (row-major [M, N])
    float sc = __ldg(scale_p);
#pragma unroll
    for (int mf = 0; mf < 4; mf++) {
#pragma unroll
        for (int ng = 0; ng < 8; ng++) {
            int m = m0 + wm * 64 + mf * 16 + (lane >> 2);
            int n = n0 + wn * 64 + ng * 8 + (lane & 3) * 2;
            float2 bb = *reinterpret_cast<const float2*>(bias + n);
            float2 v;
            v.x = acc[mf][ng][0] * sc + bb.x;
            v.y = acc[mf][ng][1] * sc + bb.y;
            *reinterpret_cast<float2*>(out + (size_t)m * N_DIM + n) = v;
            v.x = acc[mf][ng][2] * sc + bb.x;
            v.y = acc[mf][ng][3] * sc + bb.y;
            *reinterpret_cast<float2*>(out + (size_t)(m + 8) * N_DIM + n) = v;
        }
    }
#undef MBF
#undef MBE
}

// ---------------------------------------------------------------------------
// Launch
// ---------------------------------------------------------------------------
extern "C" void kernel_launch(void* const* d_in, const int* in_sizes, int n_in,
                              void* d_out, int out_size) {
    const int*   A_packed = (const int*)d_in[0];
    const int*   SFA      = (const int*)d_in[1];
    const float* scale    = (const float*)d_in[2];
    const int*   B_packed = (const int*)d_in[3];
    const int*   SFB      = (const int*)d_in[4];
    const float* bias     = (const float*)d_in[5];
    float*       out      = (float*)d_out;

    int tot = TOTA + TOTB;
    dequant_kernel<<<(tot + 255) / 256, 256>>>(A_packed, SFA, B_packed, SFB);

    static int configured = 0;
    if (!configured) {
        cudaFuncSetAttribute(gemm_kernel, cudaFuncAttributeMaxDynamicSharedMemorySize, SMEM_DYN);
        configured = 1;
    }
    dim3 grid(N_DIM / BN, M_DIM / BM);  // (32, 64)
    gemm_kernel<<<grid, NT, SMEM_DYN>>>(scale, bias, out);
}